// round 15
// baseline (speedup 1.0000x reference)
#include <cuda_runtime.h>
#include <cuda_fp16.h>
#include <cstdint>

#define NN 100000
#define NE 1600000
#define D  128
#define CAP 128          // per-node bin capacity (max degree ~48, P(>128) ~ 0)

// ---------------- scratch: __device__ globals only ----------------
__device__ int   g_is64;
__device__ int   g_cnt[NN];                       // per-node degree (atomic)
__device__ int   g_bins[(size_t)NN * CAP];        // per-node source lists
__device__ __half g_xh[(size_t)NN * D];   // gather table (fp16): feat, then layer-1 acts
__device__ __half g_ah[(size_t)NN * D];   // aggregated+normalized features (GEMM A)
__device__ __half g_bh1[D * D];           // W1^T fp16 [n][k]
__device__ __half g_bh2[D * D];           // W2^T fp16 [n][k]

// ---------------- warp-MMA helpers ----------------
__device__ __forceinline__ uint32_t smem_u32(const void* p) {
    uint32_t a;
    asm("{ .reg .u64 t; cvta.to.shared.u64 t, %1; cvt.u32.u64 %0, t; }"
        : "=r"(a) : "l"(p));
    return a;
}
__device__ __forceinline__ void ldsm_x4(uint32_t* r, uint32_t addr) {
    asm volatile("ldmatrix.sync.aligned.m8n8.x4.shared.b16 {%0,%1,%2,%3}, [%4];"
                 : "=r"(r[0]), "=r"(r[1]), "=r"(r[2]), "=r"(r[3]) : "r"(addr));
}
__device__ __forceinline__ void mma_fp16(float* c, const uint32_t* a,
                                         const uint32_t* b) {
    asm volatile(
        "mma.sync.aligned.m16n8k16.row.col.f32.f16.f16.f32 "
        "{%0,%1,%2,%3}, {%4,%5,%6,%7}, {%8,%9}, {%0,%1,%2,%3};"
        : "+f"(c[0]), "+f"(c[1]), "+f"(c[2]), "+f"(c[3])
        : "r"(a[0]), "r"(a[1]), "r"(a[2]), "r"(a[3]), "r"(b[0]), "r"(b[1]));
}

// ---------------- prep: zero cnt + feat->fp16 + W^T->fp16 + dtype detect ------
__global__ void prep_kernel(const float* __restrict__ feat,
                            const float* __restrict__ W1,
                            const float* __restrict__ W2,
                            const int*   __restrict__ ei32,
                            int n, int total4) {
    int i = blockIdx.x * blockDim.x + threadIdx.x;
    if (i < n) g_cnt[i] = 0;
    if (i < total4) {
        float4 v = ((const float4*)feat)[i];
        ((__half2*)g_xh)[2 * i]     = __floats2half2_rn(v.x, v.y);
        ((__half2*)g_xh)[2 * i + 1] = __floats2half2_rn(v.z, v.w);
    }
    if (i < D * D) {
        int nn = i >> 7, k = i & 127;
        g_bh1[nn * D + k] = __float2half_rn(W1[k * D + nn]);
        g_bh2[nn * D + k] = __float2half_rn(W2[k * D + nn]);
    }
    // dtype detect: warp 0 of block 0; int64 LE data < 2^31 -> odd words all 0
    if (blockIdx.x == 0 && threadIdx.x < 32) {
        int lane = threadIdx.x;
        int nz = ei32[2 * lane + 1] | ei32[2 * (lane + 32) + 1];
        unsigned any = __ballot_sync(0xffffffffu, nz != 0);
        if (lane == 0) g_is64 = (any == 0) ? 1 : 0;
    }
}

// ---------------- direct binning: 8 edges/thread ----------------
__global__ void fill_kernel(const int* __restrict__ ei32, int E) {
    int e = (blockIdx.x * blockDim.x + threadIdx.x) * 8;
    if (e >= E) return;
    int is64 = g_is64;
    int s[8], d[8];
    if (is64) {
        const int4* ps = (const int4*)ei32 + ((size_t)e >> 1);
        const int4* pd = (const int4*)ei32 + ((size_t)(E + e) >> 1);
        #pragma unroll
        for (int q = 0; q < 4; q++) {
            int4 a = __ldg(ps + q);
            s[2 * q] = a.x; s[2 * q + 1] = a.z;
            int4 c = __ldg(pd + q);
            d[2 * q] = c.x; d[2 * q + 1] = c.z;
        }
    } else {
        const int4* ps = (const int4*)ei32 + ((size_t)e >> 2);
        const int4* pd = (const int4*)ei32 + (((size_t)E + e) >> 2);
        #pragma unroll
        for (int q = 0; q < 2; q++) {
            int4 a = __ldg(ps + q);
            s[4 * q] = a.x; s[4 * q + 1] = a.y; s[4 * q + 2] = a.z; s[4 * q + 3] = a.w;
            int4 c = __ldg(pd + q);
            d[4 * q] = c.x; d[4 * q + 1] = c.y; d[4 * q + 2] = c.z; d[4 * q + 3] = c.w;
        }
    }
    #pragma unroll
    for (int q = 0; q < 8; q++) {
        if ((unsigned)d[q] < (unsigned)NN && (unsigned)s[q] < (unsigned)NN) {
            int pos = atomicAdd(&g_cnt[d[q]], 1);
            if (pos < CAP)                      // never triggers (max deg ~48)
                g_bins[(size_t)d[q] * CAP + pos] = s[q];
        }
    }
}

// ---------------- aggregation: warp per node, fp16 gather, fp32 accumulate ------
__global__ void aggregate_kernel(int n) {
    int node = blockIdx.x * (blockDim.x >> 5) + (threadIdx.x >> 5);
    int lane = threadIdx.x & 31;
    if (node >= n) return;
    int cnt = g_cnt[node];
    if (cnt > CAP) cnt = CAP;
    const int* bin = g_bins + (size_t)node * CAP;
    const uint2* X2 = (const uint2*)g_xh;   // 4 halves per uint2; 32 uint2 per row

    float acc0 = 0.f, acc1 = 0.f, acc2 = 0.f, acc3 = 0.f;
    int e = 0;
    for (; e + 4 <= cnt; e += 4) {
        int s0 = bin[e + 0];
        int s1 = bin[e + 1];
        int s2 = bin[e + 2];
        int s3 = bin[e + 3];
        uint2 v0 = __ldg(X2 + (size_t)s0 * 32 + lane);
        uint2 v1 = __ldg(X2 + (size_t)s1 * 32 + lane);
        uint2 v2 = __ldg(X2 + (size_t)s2 * 32 + lane);
        uint2 v3 = __ldg(X2 + (size_t)s3 * 32 + lane);
        #pragma unroll
        for (int q = 0; q < 4; q++) {
            uint2 v = (q == 0) ? v0 : (q == 1) ? v1 : (q == 2) ? v2 : v3;
            float2 f01 = __half22float2(*(__half2*)&v.x);
            float2 f23 = __half22float2(*(__half2*)&v.y);
            acc0 += f01.x; acc1 += f01.y; acc2 += f23.x; acc3 += f23.y;
        }
    }
    for (; e < cnt; e++) {
        int s = bin[e];
        uint2 v = __ldg(X2 + (size_t)s * 32 + lane);
        float2 f01 = __half22float2(*(__half2*)&v.x);
        float2 f23 = __half22float2(*(__half2*)&v.y);
        acc0 += f01.x; acc1 += f01.y; acc2 += f23.x; acc3 += f23.y;
    }
    {
        uint2 v = __ldg(X2 + (size_t)node * 32 + lane);
        float2 f01 = __half22float2(*(__half2*)&v.x);
        float2 f23 = __half22float2(*(__half2*)&v.y);
        acc0 += f01.x; acc1 += f01.y; acc2 += f23.x; acc3 += f23.y;
    }
    float inv = 1.0f / (float)(cnt + 1);
    size_t base = (size_t)node * D + lane * 4;
    *(__half2*)(g_ah + base)     = __floats2half2_rn(acc0 * inv, acc1 * inv);
    *(__half2*)(g_ah + base + 2) = __floats2half2_rn(acc2 * inv, acc3 * inv);
}

// ---------------- warp-MMA fp16 GEMM + bias + leaky relu ----------------
// block: 512 threads (16 warps, 4x4 warp grid), tile M=128 N=128 K=128.
// warp w: m0 = (w&3)*32, n0 = (w>>2)*32 -> 32x32 output, acc[2][4][4] (32 regs).
// layer==1: B = g_bh1, write fp16 acts to g_xh.  layer==2: B = g_bh2, fp32 to Out.
#define ROWB 272
#define SM_BIAS 0
#define SM_A  512
#define SM_B  (SM_A + 128 * ROWB)
#define SM_TOT (SM_B + 128 * ROWB)   // 70144 B

__global__ __launch_bounds__(512)
void gemm_mma_kernel(const float* __restrict__ bias,
                     float* __restrict__ Out, int layer, int M) {
    extern __shared__ char smem[];
    uint32_t sb = smem_u32(smem);
    int t = threadIdx.x, lane = t & 31, wid = t >> 5;

    int block_row = blockIdx.x * 128;
    int rows = M - block_row; if (rows > 128) rows = 128;

    if (t < 32) *(float4*)(smem + SM_BIAS + t * 16) = ((const float4*)bias)[t];

    {
        const __half* Wt = (layer == 1) ? g_bh1 : g_bh2;
        const uint4 z4 = make_uint4(0, 0, 0, 0);
        #pragma unroll
        for (int it = 0; it < 4; it++) {
            int i = t + it * 512;
            int r = i >> 4, c = i & 15;
            uint32_t so = r * ROWB + c * 16;
            uint4 va = z4;
            if (r < rows)
                va = ((const uint4*)g_ah)[((size_t)(block_row + r) * 16) + c];
            *(uint4*)(smem + SM_A + so) = va;
            *(uint4*)(smem + SM_B + so) = ((const uint4*)Wt)[(size_t)r * 16 + c];
        }
    }
    __syncthreads();

    int m0 = (wid & 3) * 32;
    int n0 = (wid >> 2) * 32;

    float acc[2][4][4];
    #pragma unroll
    for (int ma = 0; ma < 2; ma++)
        #pragma unroll
        for (int na = 0; na < 4; na++)
            #pragma unroll
            for (int q = 0; q < 4; q++) acc[ma][na][q] = 0.f;

    uint32_t aAddr[2];
    #pragma unroll
    for (int ma = 0; ma < 2; ma++) {
        int r = m0 + ma * 16 + (lane & 15);
        aAddr[ma] = sb + SM_A + r * ROWB + (lane >> 4) * 16;
    }
    uint32_t bAddr[2];
    {
        int q = lane >> 3;
        int nrow_off = ((q & 2) << 2) + (lane & 7);
        int kadd = (q & 1) * 8;
        #pragma unroll
        for (int p = 0; p < 2; p++) {
            int nrow = n0 + p * 16 + nrow_off;
            bAddr[p] = sb + SM_B + nrow * ROWB + kadd * 2;
        }
    }

    #pragma unroll
    for (int ks = 0; ks < 8; ks++) {
        uint32_t kb = ks * 32;
        uint32_t a[2][4], b[4][2];
        #pragma unroll
        for (int ma = 0; ma < 2; ma++)
            ldsm_x4(a[ma], aAddr[ma] + kb);
        #pragma unroll
        for (int p = 0; p < 2; p++) {
            uint32_t rh[4];
            ldsm_x4(rh, bAddr[p] + kb);
            b[2 * p][0] = rh[0]; b[2 * p][1] = rh[1];
            b[2 * p + 1][0] = rh[2]; b[2 * p + 1][1] = rh[3];
        }
        #pragma unroll
        for (int ma = 0; ma < 2; ma++)
            #pragma unroll
            for (int na = 0; na < 4; na++)
                mma_fp16(acc[ma][na], a[ma], b[na]);
    }

    const float* bsm = (const float*)(smem + SM_BIAS);
    int rbase = m0 + (lane >> 2);
    int cpair = (lane & 3) * 2;
    #pragma unroll
    for (int ma = 0; ma < 2; ma++) {
        #pragma unroll
        for (int na = 0; na < 4; na++) {
            int col = n0 + na * 8 + cpair;
            float bx = bsm[col], by = bsm[col + 1];
            #pragma unroll
            for (int half = 0; half < 2; half++) {
                int r = rbase + ma * 16 + half * 8;
                if (r < rows) {
                    float v0 = acc[ma][na][half * 2]     + bx;
                    float v1 = acc[ma][na][half * 2 + 1] + by;
                    float o0 = (v0 >= 0.f) ? v0 : 0.01f * v0;
                    float o1 = (v1 >= 0.f) ? v1 : 0.01f * v1;
                    size_t idx = (size_t)(block_row + r) * D + col;
                    if (layer == 1) {
                        *(__half2*)(g_xh + idx) = __floats2half2_rn(o0, o1);
                    } else {
                        *(float2*)(Out + idx) = make_float2(o0, o1);
                    }
                }
            }
        }
    }
}

// ---------------- launch ----------------
extern "C" void kernel_launch(void* const* d_in, const int* in_sizes, int n_in,
                              void* d_out, int out_size) {
    const float* feat = (const float*)d_in[0];
    const int*   ei32 = (const int*)d_in[1];   // int32 OR int64 (auto-detected)
    const float* W1   = (const float*)d_in[2];
    const float* b1   = (const float*)d_in[3];
    const float* W2   = (const float*)d_in[4];
    const float* b2   = (const float*)d_in[5];
    float* out = (float*)d_out;

    int N = in_sizes[0] / D;      // 100000
    int E = in_sizes[1] / 2;      // 1600000
    int total4 = N * D / 4;

    cudaFuncSetAttribute(gemm_mma_kernel,
                         cudaFuncAttributeMaxDynamicSharedMemorySize, SM_TOT);

    // 1. prep (zero cnt, feat->fp16, W^T->fp16 both layers, dtype detect)
    prep_kernel<<<(total4 + 255) / 256, 256>>>(feat, W1, W2, ei32, N, total4);
    // 2. direct binning (no count/scan passes)
    int edge8_blocks = (E / 8 + 255) / 256;
    fill_kernel<<<edge8_blocks, 256>>>(ei32, E);

    int agg_blocks  = (N + 7) / 8;
    int gemm_blocks = (N + 127) / 128;

    // 3-4. layer 1: aggregate(g_xh)->g_ah ; GEMM(W1) -> g_xh (fp16 activations)
    aggregate_kernel<<<agg_blocks, 256>>>(N);
    gemm_mma_kernel<<<gemm_blocks, 512, SM_TOT>>>(b1, out, 1, N);
    // 5-6. layer 2: aggregate(g_xh)->g_ah ; GEMM(W2) -> out (fp32)
    aggregate_kernel<<<agg_blocks, 256>>>(N);
    gemm_mma_kernel<<<gemm_blocks, 512, SM_TOT>>>(b2, out, 2, N);
}

// round 16
// speedup vs baseline: 1.0165x; 1.0165x over previous
#include <cuda_runtime.h>
#include <cuda_fp16.h>
#include <cstdint>

#define NN 100000
#define NE 1600000
#define D  128
#define CAP 128          // per-node bin capacity (max degree ~48, P(>128) ~ 0)

// ---------------- scratch: __device__ globals only ----------------
__device__ int   g_is64;
__device__ int   g_cnt[NN];                       // per-node degree (atomic)
__device__ int   g_bins[(size_t)NN * CAP];        // per-node source lists
__device__ __half g_xh[(size_t)NN * D];   // gather table (fp16): feat, then layer-1 acts
__device__ __half g_ah[(size_t)NN * D];   // aggregated+normalized features (GEMM A)
__device__ __half g_bh1[D * D];           // W1^T fp16 [n][k]
__device__ __half g_bh2[D * D];           // W2^T fp16 [n][k]

// ---------------- warp-MMA + cp.async helpers ----------------
__device__ __forceinline__ uint32_t smem_u32(const void* p) {
    uint32_t a;
    asm("{ .reg .u64 t; cvta.to.shared.u64 t, %1; cvt.u32.u64 %0, t; }"
        : "=r"(a) : "l"(p));
    return a;
}
__device__ __forceinline__ void ldsm_x4(uint32_t* r, uint32_t addr) {
    asm volatile("ldmatrix.sync.aligned.m8n8.x4.shared.b16 {%0,%1,%2,%3}, [%4];"
                 : "=r"(r[0]), "=r"(r[1]), "=r"(r[2]), "=r"(r[3]) : "r"(addr));
}
__device__ __forceinline__ void mma_fp16(float* c, const uint32_t* a,
                                         const uint32_t* b) {
    asm volatile(
        "mma.sync.aligned.m16n8k16.row.col.f32.f16.f16.f32 "
        "{%0,%1,%2,%3}, {%4,%5,%6,%7}, {%8,%9}, {%0,%1,%2,%3};"
        : "+f"(c[0]), "+f"(c[1]), "+f"(c[2]), "+f"(c[3])
        : "r"(a[0]), "r"(a[1]), "r"(a[2]), "r"(a[3]), "r"(b[0]), "r"(b[1]));
}
// 16B global->shared copy; src_bytes = 16 (copy) or 0 (zero-fill)
__device__ __forceinline__ void cp_async16(uint32_t smem_addr, const void* gptr,
                                           int src_bytes) {
    asm volatile("cp.async.ca.shared.global [%0], [%1], 16, %2;"
                 :: "r"(smem_addr), "l"(gptr), "r"(src_bytes));
}
#define CP_ASYNC_COMMIT() asm volatile("cp.async.commit_group;" ::: "memory")
#define CP_ASYNC_WAIT0()  asm volatile("cp.async.wait_group 0;" ::: "memory")

// ---------------- prep: zero cnt + feat->fp16 + W^T->fp16 + dtype detect ------
__global__ void prep_kernel(const float* __restrict__ feat,
                            const float* __restrict__ W1,
                            const float* __restrict__ W2,
                            const int*   __restrict__ ei32,
                            int n, int total4) {
    int i = blockIdx.x * blockDim.x + threadIdx.x;
    if (i < n) g_cnt[i] = 0;
    if (i < total4) {
        float4 v = ((const float4*)feat)[i];
        ((__half2*)g_xh)[2 * i]     = __floats2half2_rn(v.x, v.y);
        ((__half2*)g_xh)[2 * i + 1] = __floats2half2_rn(v.z, v.w);
    }
    if (i < D * D) {
        int nn = i >> 7, k = i & 127;
        g_bh1[nn * D + k] = __float2half_rn(W1[k * D + nn]);
        g_bh2[nn * D + k] = __float2half_rn(W2[k * D + nn]);
    }
    // dtype detect: warp 0 of block 0; int64 LE data < 2^31 -> odd words all 0
    if (blockIdx.x == 0 && threadIdx.x < 32) {
        int lane = threadIdx.x;
        int nz = ei32[2 * lane + 1] | ei32[2 * (lane + 32) + 1];
        unsigned any = __ballot_sync(0xffffffffu, nz != 0);
        if (lane == 0) g_is64 = (any == 0) ? 1 : 0;
    }
}

// ---------------- direct binning: 8 edges/thread ----------------
__global__ void fill_kernel(const int* __restrict__ ei32, int E) {
    int e = (blockIdx.x * blockDim.x + threadIdx.x) * 8;
    if (e >= E) return;
    int is64 = g_is64;
    int s[8], d[8];
    if (is64) {
        const int4* ps = (const int4*)ei32 + ((size_t)e >> 1);
        const int4* pd = (const int4*)ei32 + ((size_t)(E + e) >> 1);
        #pragma unroll
        for (int q = 0; q < 4; q++) {
            int4 a = __ldg(ps + q);
            s[2 * q] = a.x; s[2 * q + 1] = a.z;
            int4 c = __ldg(pd + q);
            d[2 * q] = c.x; d[2 * q + 1] = c.z;
        }
    } else {
        const int4* ps = (const int4*)ei32 + ((size_t)e >> 2);
        const int4* pd = (const int4*)ei32 + (((size_t)E + e) >> 2);
        #pragma unroll
        for (int q = 0; q < 2; q++) {
            int4 a = __ldg(ps + q);
            s[4 * q] = a.x; s[4 * q + 1] = a.y; s[4 * q + 2] = a.z; s[4 * q + 3] = a.w;
            int4 c = __ldg(pd + q);
            d[4 * q] = c.x; d[4 * q + 1] = c.y; d[4 * q + 2] = c.z; d[4 * q + 3] = c.w;
        }
    }
    #pragma unroll
    for (int q = 0; q < 8; q++) {
        if ((unsigned)d[q] < (unsigned)NN && (unsigned)s[q] < (unsigned)NN) {
            int pos = atomicAdd(&g_cnt[d[q]], 1);
            if (pos < CAP)                      // never triggers (max deg ~48)
                g_bins[(size_t)d[q] * CAP + pos] = s[q];
        }
    }
}

// ---------------- aggregation: warp per node, fp16 gather, fp32 accumulate ------
__global__ void aggregate_kernel(int n) {
    int node = blockIdx.x * (blockDim.x >> 5) + (threadIdx.x >> 5);
    int lane = threadIdx.x & 31;
    if (node >= n) return;
    int cnt = g_cnt[node];
    if (cnt > CAP) cnt = CAP;
    const int* bin = g_bins + (size_t)node * CAP;
    const uint2* X2 = (const uint2*)g_xh;   // 4 halves per uint2; 32 uint2 per row

    float acc0 = 0.f, acc1 = 0.f, acc2 = 0.f, acc3 = 0.f;
    int e = 0;
    for (; e + 4 <= cnt; e += 4) {
        int s0 = bin[e + 0];
        int s1 = bin[e + 1];
        int s2 = bin[e + 2];
        int s3 = bin[e + 3];
        uint2 v0 = __ldg(X2 + (size_t)s0 * 32 + lane);
        uint2 v1 = __ldg(X2 + (size_t)s1 * 32 + lane);
        uint2 v2 = __ldg(X2 + (size_t)s2 * 32 + lane);
        uint2 v3 = __ldg(X2 + (size_t)s3 * 32 + lane);
        #pragma unroll
        for (int q = 0; q < 4; q++) {
            uint2 v = (q == 0) ? v0 : (q == 1) ? v1 : (q == 2) ? v2 : v3;
            float2 f01 = __half22float2(*(__half2*)&v.x);
            float2 f23 = __half22float2(*(__half2*)&v.y);
            acc0 += f01.x; acc1 += f01.y; acc2 += f23.x; acc3 += f23.y;
        }
    }
    for (; e < cnt; e++) {
        int s = bin[e];
        uint2 v = __ldg(X2 + (size_t)s * 32 + lane);
        float2 f01 = __half22float2(*(__half2*)&v.x);
        float2 f23 = __half22float2(*(__half2*)&v.y);
        acc0 += f01.x; acc1 += f01.y; acc2 += f23.x; acc3 += f23.y;
    }
    {
        uint2 v = __ldg(X2 + (size_t)node * 32 + lane);
        float2 f01 = __half22float2(*(__half2*)&v.x);
        float2 f23 = __half22float2(*(__half2*)&v.y);
        acc0 += f01.x; acc1 += f01.y; acc2 += f23.x; acc3 += f23.y;
    }
    float inv = 1.0f / (float)(cnt + 1);
    size_t base = (size_t)node * D + lane * 4;
    *(__half2*)(g_ah + base)     = __floats2half2_rn(acc0 * inv, acc1 * inv);
    *(__half2*)(g_ah + base + 2) = __floats2half2_rn(acc2 * inv, acc3 * inv);
}

// ---------------- warp-MMA fp16 GEMM + bias + leaky relu ----------------
// block: 512 threads (16 warps, 4x4 warp grid), tile M=128 N=128 K=128.
// Tiles staged via cp.async (no reg round-trip through L1).
// layer==1: B = g_bh1, write fp16 acts to g_xh.  layer==2: B = g_bh2, fp32 to Out.
#define ROWB 272
#define SM_BIAS 0
#define SM_A  512
#define SM_B  (SM_A + 128 * ROWB)
#define SM_TOT (SM_B + 128 * ROWB)   // 70144 B

__global__ __launch_bounds__(512)
void gemm_mma_kernel(const float* __restrict__ bias,
                     float* __restrict__ Out, int layer, int M) {
    extern __shared__ char smem[];
    uint32_t sb = smem_u32(smem);
    int t = threadIdx.x, lane = t & 31, wid = t >> 5;

    int block_row = blockIdx.x * 128;
    int rows = M - block_row; if (rows > 128) rows = 128;

    if (t < 32) *(float4*)(smem + SM_BIAS + t * 16) = ((const float4*)bias)[t];

    // stage A and B via cp.async: row r (128), 16B chunk c (16)
    {
        const char* Wt = (const char*)((layer == 1) ? g_bh1 : g_bh2);
        const char* Ab = (const char*)g_ah;
        #pragma unroll
        for (int it = 0; it < 4; it++) {
            int i = t + it * 512;
            int r = i >> 4, c = i & 15;
            uint32_t so = r * ROWB + c * 16;
            cp_async16(sb + SM_A + so,
                       Ab + ((size_t)(block_row + r) * 256 + c * 16),
                       (r < rows) ? 16 : 0);
            cp_async16(sb + SM_B + so, Wt + ((size_t)r * 256 + c * 16), 16);
        }
    }
    CP_ASYNC_COMMIT();
    CP_ASYNC_WAIT0();
    __syncthreads();

    int m0 = (wid & 3) * 32;
    int n0 = (wid >> 2) * 32;

    float acc[2][4][4];
    #pragma unroll
    for (int ma = 0; ma < 2; ma++)
        #pragma unroll
        for (int na = 0; na < 4; na++)
            #pragma unroll
            for (int q = 0; q < 4; q++) acc[ma][na][q] = 0.f;

    uint32_t aAddr[2];
    #pragma unroll
    for (int ma = 0; ma < 2; ma++) {
        int r = m0 + ma * 16 + (lane & 15);
        aAddr[ma] = sb + SM_A + r * ROWB + (lane >> 4) * 16;
    }
    uint32_t bAddr[2];
    {
        int q = lane >> 3;
        int nrow_off = ((q & 2) << 2) + (lane & 7);
        int kadd = (q & 1) * 8;
        #pragma unroll
        for (int p = 0; p < 2; p++) {
            int nrow = n0 + p * 16 + nrow_off;
            bAddr[p] = sb + SM_B + nrow * ROWB + kadd * 2;
        }
    }

    #pragma unroll
    for (int ks = 0; ks < 8; ks++) {
        uint32_t kb = ks * 32;
        uint32_t a[2][4], b[4][2];
        #pragma unroll
        for (int ma = 0; ma < 2; ma++)
            ldsm_x4(a[ma], aAddr[ma] + kb);
        #pragma unroll
        for (int p = 0; p < 2; p++) {
            uint32_t rh[4];
            ldsm_x4(rh, bAddr[p] + kb);
            b[2 * p][0] = rh[0]; b[2 * p][1] = rh[1];
            b[2 * p + 1][0] = rh[2]; b[2 * p + 1][1] = rh[3];
        }
        #pragma unroll
        for (int ma = 0; ma < 2; ma++)
            #pragma unroll
            for (int na = 0; na < 4; na++)
                mma_fp16(acc[ma][na], a[ma], b[na]);
    }

    const float* bsm = (const float*)(smem + SM_BIAS);
    int rbase = m0 + (lane >> 2);
    int cpair = (lane & 3) * 2;
    #pragma unroll
    for (int ma = 0; ma < 2; ma++) {
        #pragma unroll
        for (int na = 0; na < 4; na++) {
            int col = n0 + na * 8 + cpair;
            float bx = bsm[col], by = bsm[col + 1];
            #pragma unroll
            for (int half = 0; half < 2; half++) {
                int r = rbase + ma * 16 + half * 8;
                if (r < rows) {
                    float v0 = acc[ma][na][half * 2]     + bx;
                    float v1 = acc[ma][na][half * 2 + 1] + by;
                    float o0 = (v0 >= 0.f) ? v0 : 0.01f * v0;
                    float o1 = (v1 >= 0.f) ? v1 : 0.01f * v1;
                    size_t idx = (size_t)(block_row + r) * D + col;
                    if (layer == 1) {
                        *(__half2*)(g_xh + idx) = __floats2half2_rn(o0, o1);
                    } else {
                        *(float2*)(Out + idx) = make_float2(o0, o1);
                    }
                }
            }
        }
    }
}

// ---------------- launch ----------------
extern "C" void kernel_launch(void* const* d_in, const int* in_sizes, int n_in,
                              void* d_out, int out_size) {
    const float* feat = (const float*)d_in[0];
    const int*   ei32 = (const int*)d_in[1];   // int32 OR int64 (auto-detected)
    const float* W1   = (const float*)d_in[2];
    const float* b1   = (const float*)d_in[3];
    const float* W2   = (const float*)d_in[4];
    const float* b2   = (const float*)d_in[5];
    float* out = (float*)d_out;

    int N = in_sizes[0] / D;      // 100000
    int E = in_sizes[1] / 2;      // 1600000
    int total4 = N * D / 4;

    cudaFuncSetAttribute(gemm_mma_kernel,
                         cudaFuncAttributeMaxDynamicSharedMemorySize, SM_TOT);

    // 1. prep (zero cnt, feat->fp16, W^T->fp16 both layers, dtype detect)
    prep_kernel<<<(total4 + 255) / 256, 256>>>(feat, W1, W2, ei32, N, total4);
    // 2. direct binning (no count/scan passes)
    int edge8_blocks = (E / 8 + 255) / 256;
    fill_kernel<<<edge8_blocks, 256>>>(ei32, E);

    int agg_blocks  = (N + 7) / 8;
    int gemm_blocks = (N + 127) / 128;

    // 3-4. layer 1: aggregate(g_xh)->g_ah ; GEMM(W1) -> g_xh (fp16 activations)
    aggregate_kernel<<<agg_blocks, 256>>>(N);
    gemm_mma_kernel<<<gemm_blocks, 512, SM_TOT>>>(b1, out, 1, N);
    // 5-6. layer 2: aggregate(g_xh)->g_ah ; GEMM(W2) -> out (fp32)
    aggregate_kernel<<<agg_blocks, 256>>>(N);
    gemm_mma_kernel<<<gemm_blocks, 512, SM_TOT>>>(b2, out, 2, N);
}